// round 2
// baseline (speedup 1.0000x reference)
#include <cuda_runtime.h>
#include <cstdint>

// Problem constants: B=32, S=2048, F=512. Output reduces to per-row one-hot
// of argmax(logits + gumbel): the straight-through mask is exactly one-hot
// in fp32 (error ~2^-23 at the hot position), and the top-K(=104857)
// "zero the smallest" scatter only touches entries that are already exactly
// zero (1,046,528 zeros per batch >> K). So: argmax per row + one-hot write.

static constexpr int F_DIM   = 512;
static constexpr int F4      = F_DIM / 4;        // 128 float4 per row
static constexpr int ROWS    = 32 * 2048;        // 65536
static constexpr int WARPS_B = 8;                // warps (rows) per block
static constexpr int THREADS = WARPS_B * 32;

__device__ __forceinline__ unsigned int float_ord(float x) {
    unsigned int b = __float_as_uint(x);
    // monotonic total order on floats as unsigned ints
    return (b & 0x80000000u) ? ~b : (b | 0x80000000u);
}

__global__ __launch_bounds__(THREADS)
void onehot_argmax_kernel(const float4* __restrict__ logits,
                          const float4* __restrict__ gumbel,
                          float4* __restrict__ out) {
    const int warp = blockIdx.x * WARPS_B + (threadIdx.x >> 5);
    const int lane = threadIdx.x & 31;
    // warp == row index in [0, ROWS)
    const size_t base = (size_t)warp * F4;

    unsigned long long bestkey = 0ull;

    // Each lane covers 4 strided float4 chunks => 16 elements.
    // Full unroll lets ptxas front-batch all 8 loads (MLP=8).
    #pragma unroll
    for (int it = 0; it < 4; it++) {
        const int off = it * 32 + lane;          // float4 index within row
        const float4 a = logits[base + off];
        const float4 g = gumbel[base + off];
        const int e = off * 4;                   // element index of .x
        float s[4];
        s[0] = a.x + g.x; s[1] = a.y + g.y; s[2] = a.z + g.z; s[3] = a.w + g.w;
        #pragma unroll
        for (int c = 0; c < 4; c++) {
            // inverted index in low bits: on value ties, smaller index wins
            unsigned long long k =
                ((unsigned long long)float_ord(s[c]) << 32) |
                (unsigned int)(F_DIM - 1 - (e + c));
            bestkey = (k > bestkey) ? k : bestkey;
        }
    }

    // xor-butterfly max-reduce: every lane ends with the row's best key
    #pragma unroll
    for (int o = 16; o > 0; o >>= 1) {
        unsigned long long other = __shfl_xor_sync(0xFFFFFFFFu, bestkey, o);
        bestkey = (other > bestkey) ? other : bestkey;
    }

    const int best_idx = F_DIM - 1 - (int)(bestkey & 0xFFFFFFFFu);

    // Write one-hot row, fully coalesced float4 stores.
    #pragma unroll
    for (int it = 0; it < 4; it++) {
        const int off = it * 32 + lane;
        const int e = off * 4;
        float4 v = make_float4(0.f, 0.f, 0.f, 0.f);
        const int d = best_idx - e;
        if ((unsigned)d < 4u) {
            (&v.x)[d] = 1.0f;
        }
        out[base + off] = v;
    }
}

extern "C" void kernel_launch(void* const* d_in, const int* in_sizes, int n_in,
                              void* d_out, int out_size) {
    const float4* logits = (const float4*)d_in[0];
    const float4* gumbel = (const float4*)d_in[1];
    float4* out = (float4*)d_out;

    const int blocks = ROWS / WARPS_B;  // 8192
    onehot_argmax_kernel<<<blocks, THREADS>>>(logits, gumbel, out);
}